// round 15
// baseline (speedup 1.0000x reference)
#include <cuda_runtime.h>

// CrossNet closed form, ONE WARP PER ROW — no block-level synchronization
// in the hot path.
//   d_k = x . w_k ; c12=b1.w2, c13=b1.w3, c23=b2.w3 (per-CTA prologue)
//   a1 = d1+1; a2 = a1*d2+c12+1; a3 = a2*(a1*d3+c13)+c23+1
//   out = (a1*a2*a3)*x + (a2*a3)*b1 + a3*b2 + b3
// B=16384, D=2048 fp32. 256 threads = 8 warps/CTA, 2048 CTAs, 1 row/warp.
// Phase 1: stream row, accumulate 3 dots (x not kept in registers).
// Warp butterfly (15 SHFL). All lanes compute coefficients redundantly.
// Phase 2: re-read row (L2 hit; fetched ~1us earlier) + fused epilogue.
// Warps fully independent -> continuous DRAM request flow.

#define D 2048
#define VEC (D / 4)        // 512 float4 per row
#define THREADS 256
#define WPC (THREADS / 32) // 8 warps per CTA
#define CHUNKS (VEC / 32)  // 16 float4 per lane

__device__ __forceinline__ float dot4(float4 a, float4 b) {
    return a.x*b.x + a.y*b.y + a.z*b.z + a.w*b.w;
}

__global__ __launch_bounds__(THREADS, 4)
void crossnet_kernel(const float4* __restrict__ x,
                     const float4* __restrict__ w1, const float4* __restrict__ b1,
                     const float4* __restrict__ w2, const float4* __restrict__ b2,
                     const float4* __restrict__ w3, const float4* __restrict__ b3,
                     float4* __restrict__ out)
{
    __shared__ float4 shq[WPC];   // per-warp (c12, c13, c23) partials

    const int t    = threadIdx.x;
    const int lane = t & 31;
    const int wid  = t >> 5;

    // ---- prologue: cross constants c12=b1.w2, c13=b1.w3, c23=b2.w3 ----
    {
        float q12 = 0.f, q13 = 0.f, q23 = 0.f;
        #pragma unroll
        for (int i = 0; i < VEC; i += THREADS) {
            const float4 bv1 = __ldg(&b1[t + i]);
            const float4 bv2 = __ldg(&b2[t + i]);
            const float4 wv2 = __ldg(&w2[t + i]);
            const float4 wv3 = __ldg(&w3[t + i]);
            q12 += dot4(bv1, wv2);
            q13 += dot4(bv1, wv3);
            q23 += dot4(bv2, wv3);
        }
        #pragma unroll
        for (int off = 16; off > 0; off >>= 1) {
            q12 += __shfl_xor_sync(0xFFFFFFFFu, q12, off);
            q13 += __shfl_xor_sync(0xFFFFFFFFu, q13, off);
            q23 += __shfl_xor_sync(0xFFFFFFFFu, q23, off);
        }
        if (lane == 0) shq[wid] = make_float4(q12, q13, q23, 0.0f);
    }
    __syncthreads();   // the ONLY block barrier; outside the hot path

    float c12 = 0.f, c13 = 0.f, c23 = 0.f;
    #pragma unroll
    for (int j = 0; j < WPC; ++j) {       // broadcast LDS, conflict-free
        const float4 q = shq[j];
        c12 += q.x; c13 += q.y; c23 += q.z;
    }

    // ---- one row per warp ----
    const int row = blockIdx.x * WPC + wid;
    const float4* xr = x + (size_t)row * VEC;

    // Phase 1: stream row, accumulate three dots (x not retained)
    float p1 = 0.f, p2 = 0.f, p3 = 0.f;
    #pragma unroll
    for (int i = 0; i < CHUNKS; ++i) {
        const int idx = lane + 32 * i;
        const float4 xv = __ldg(&xr[idx]);
        p1 += dot4(xv, __ldg(&w1[idx]));
        p2 += dot4(xv, __ldg(&w2[idx]));
        p3 += dot4(xv, __ldg(&w3[idx]));
    }

    // warp butterfly: all lanes end with full dots
    #pragma unroll
    for (int off = 16; off > 0; off >>= 1) {
        p1 += __shfl_xor_sync(0xFFFFFFFFu, p1, off);
        p2 += __shfl_xor_sync(0xFFFFFFFFu, p2, off);
        p3 += __shfl_xor_sync(0xFFFFFFFFu, p3, off);
    }

    // coefficients (computed redundantly by every lane; no communication)
    const float a1 = p1 + 1.0f;
    const float a2 = fmaf(a1, p2, c12) + 1.0f;
    const float a3 = fmaf(a2, fmaf(a1, p3, c13), c23) + 1.0f;
    const float k2 = a3;
    const float k1 = a2 * a3;
    const float m  = a1 * k1;

    // Phase 2: re-read row (L2 hit) + fused epilogue
    float4* orow = out + (size_t)row * VEC;
    #pragma unroll
    for (int i = 0; i < CHUNKS; ++i) {
        const int idx = lane + 32 * i;
        const float4 xv  = __ldg(&xr[idx]);
        const float4 bv1 = __ldg(&b1[idx]);
        const float4 bv2 = __ldg(&b2[idx]);
        const float4 bv3 = __ldg(&b3[idx]);
        float4 o;
        o.x = fmaf(xv.x, m, fmaf(bv1.x, k1, fmaf(bv2.x, k2, bv3.x)));
        o.y = fmaf(xv.y, m, fmaf(bv1.y, k1, fmaf(bv2.y, k2, bv3.y)));
        o.z = fmaf(xv.z, m, fmaf(bv1.z, k1, fmaf(bv2.z, k2, bv3.z)));
        o.w = fmaf(xv.w, m, fmaf(bv1.w, k1, fmaf(bv2.w, k2, bv3.w)));
        __stcs(&orow[idx], o);
    }
}

extern "C" void kernel_launch(void* const* d_in, const int* in_sizes, int n_in,
                              void* d_out, int out_size)
{
    const float4* x  = (const float4*)d_in[0];
    const float4* w1 = (const float4*)d_in[1];
    const float4* b1 = (const float4*)d_in[2];
    const float4* w2 = (const float4*)d_in[3];
    const float4* b2 = (const float4*)d_in[4];
    const float4* w3 = (const float4*)d_in[5];
    const float4* b3 = (const float4*)d_in[6];
    float4* out = (float4*)d_out;

    const int B = in_sizes[0] / D;        // 16384 rows
    const int grid = B / WPC;             // 2048 CTAs, one row per warp
    crossnet_kernel<<<grid, THREADS>>>(x, w1, b1, w2, b2, w3, b3, out);
}

// round 16
// speedup vs baseline: 1.4083x; 1.4083x over previous
#include <cuda_runtime.h>
#include <cstdint>

// CrossNet closed form, persistent CTAs + 3-stage cp.async smem pipeline.
//   d_k = x . w_k ; c12=b1.w2, c13=b1.w3, c23=b2.w3 (prologue, per CTA)
//   a1 = d1+1; a2 = a1*d2+c12+1; a3 = a2*(a1*d3+c13)+c23+1
//   out = (a1*a2*a3)*x + (a2*a3)*b1 + a3*b2 + b3
// B=16384, D=2048 fp32. R=4 rows/tile, 512 threads, 296 persistent CTAs.
// cp.async (LDGSTS) streams tiles gmem->smem with NO registers and NO
// scoreboard: 3-stage ring gives a prefetch distance of 2 full tile bodies.
// Each thread copies exactly the chunks it later reads -> wait_group alone
// orders producer/consumer; no extra barriers. Weights in registers.
// Barrier protocol (512 total arrivals each):
//   bar1: warps 1..15 arrive (480) + warp0 sync (32)
//   bar2: warp0 arrive (32) + warps 1..15 sync (480)

#define D 2048
#define VEC (D / 4)              // 512 float4 per row
#define THREADS 512
#define NWARP (THREADS / 32)     // 16
#define R 4
#define NSTAGE 3
#define NCTA 296                 // 2 per SM * 148 SMs
#define TILE_F4 (R * VEC)        // 2048 float4 = 32 KB per tile
#define DYN_BYTES ((NSTAGE * TILE_F4 + 2 * VEC) * 16)  // 114688 B

#define BAR_ARRIVE(id) asm volatile("bar.arrive %0, %1;" :: "r"(id), "r"(THREADS) : "memory")
#define BAR_SYNC(id)   asm volatile("bar.sync %0, %1;"   :: "r"(id), "r"(THREADS) : "memory")

__device__ __forceinline__ float dot4(float4 a, float4 b) {
    return a.x*b.x + a.y*b.y + a.z*b.z + a.w*b.w;
}

__device__ __forceinline__ void cp16(uint32_t smem_dst, const float4* gsrc) {
    asm volatile("cp.async.cg.shared.global [%0], [%1], 16;"
                 :: "r"(smem_dst), "l"(gsrc) : "memory");
}

__global__ __launch_bounds__(THREADS, 2)
void crossnet_kernel(const float4* __restrict__ x,
                     const float4* __restrict__ w1, const float4* __restrict__ b1,
                     const float4* __restrict__ w2, const float4* __restrict__ b2,
                     const float4* __restrict__ w3, const float4* __restrict__ b3,
                     float4* __restrict__ out, int ntiles)
{
    extern __shared__ float4 dyn[];
    float4* buf = dyn;                         // [NSTAGE][TILE_F4]
    float4* sb1 = dyn + NSTAGE * TILE_F4;      // bias1 (8 KB)
    float4* sb2 = sb1 + VEC;                   // bias2 (8 KB)

    __shared__ float4 shp1[NWARP], shp2[NWARP], shp3[NWARP];
    __shared__ float4 sh_c[R];
    __shared__ float  sh_k[3];

    const int t    = threadIdx.x;
    const int lane = t & 31;
    const int wid  = t >> 5;

    // ---- weights + b3 in registers (loop-invariant) ----
    const float4 wv1 = __ldg(&w1[t]);
    const float4 wv2 = __ldg(&w2[t]);
    const float4 wv3 = __ldg(&w3[t]);
    const float4 bv3 = __ldg(&b3[t]);

    // ---- prologue: stage b1,b2 + cross constants ----
    {
        const float4 bq1 = __ldg(&b1[t]);
        const float4 bq2 = __ldg(&b2[t]);
        sb1[t] = bq1; sb2[t] = bq2;

        float q12 = dot4(bq1, wv2);
        float q13 = dot4(bq1, wv3);
        float q23 = dot4(bq2, wv3);
        #pragma unroll
        for (int off = 16; off > 0; off >>= 1) {
            q12 += __shfl_xor_sync(0xFFFFFFFFu, q12, off);
            q13 += __shfl_xor_sync(0xFFFFFFFFu, q13, off);
            q23 += __shfl_xor_sync(0xFFFFFFFFu, q23, off);
        }
        if (lane == 0) shp1[wid] = make_float4(q12, q13, q23, 0.0f);
    }
    __syncthreads();
    if (wid == 0) {
        float4 v = (lane < NWARP) ? shp1[lane] : make_float4(0.f, 0.f, 0.f, 0.f);
        #pragma unroll
        for (int off = 8; off > 0; off >>= 1) {
            v.x += __shfl_xor_sync(0xFFFFFFFFu, v.x, off);
            v.y += __shfl_xor_sync(0xFFFFFFFFu, v.y, off);
            v.z += __shfl_xor_sync(0xFFFFFFFFu, v.z, off);
        }
        if (lane == 0) { sh_k[0] = v.x; sh_k[1] = v.y; sh_k[2] = v.z; }
    }
    __syncthreads();

    // ---- cp.async pipeline prologue: stage first 2 tiles ----
    const uint32_t buf_s = (uint32_t)__cvta_generic_to_shared(buf);
    #pragma unroll
    for (int s = 0; s < NSTAGE - 1; ++s) {
        const int tl = blockIdx.x + s * gridDim.x;
        if (tl < ntiles) {
            const float4* src = x + (size_t)tl * TILE_F4 + t;
            const uint32_t dst = buf_s + (s * TILE_F4 + t) * 16;
            #pragma unroll
            for (int r = 0; r < R; ++r)
                cp16(dst + r * VEC * 16, src + r * VEC);
        }
        asm volatile("cp.async.commit_group;" ::: "memory");
    }

    int stage = 0;
    for (int tile = blockIdx.x; tile < ntiles; tile += gridDim.x) {
        // ---- issue stage+2 tile (fire-and-forget) ----
        {
            const int tl = tile + 2 * gridDim.x;
            int sb = stage + 2; if (sb >= NSTAGE) sb -= NSTAGE;
            if (tl < ntiles) {
                const float4* src = x + (size_t)tl * TILE_F4 + t;
                const uint32_t dst = buf_s + (sb * TILE_F4 + t) * 16;
                #pragma unroll
                for (int r = 0; r < R; ++r)
                    cp16(dst + r * VEC * 16, src + r * VEC);
            }
            asm volatile("cp.async.commit_group;" ::: "memory");
        }
        // ---- wait for current tile (<=2 groups pending) ----
        asm volatile("cp.async.wait_group 2;" ::: "memory");

        const float4* cb = buf + stage * TILE_F4;

        // ---- three dots per row from smem (weights in registers) ----
        float q1[R], q2[R], q3[R];
        #pragma unroll
        for (int r = 0; r < R; ++r) {
            const float4 xv = cb[r * VEC + t];
            q1[r] = dot4(xv, wv1);
            q2[r] = dot4(xv, wv2);
            q3[r] = dot4(xv, wv3);
        }
        #pragma unroll
        for (int off = 16; off > 0; off >>= 1) {
            #pragma unroll
            for (int r = 0; r < R; ++r) {
                q1[r] += __shfl_xor_sync(0xFFFFFFFFu, q1[r], off);
                q2[r] += __shfl_xor_sync(0xFFFFFFFFu, q2[r], off);
                q3[r] += __shfl_xor_sync(0xFFFFFFFFu, q3[r], off);
            }
        }
        if (lane == 0) {
            shp1[wid] = make_float4(q1[0], q1[1], q1[2], q1[3]);
            shp2[wid] = make_float4(q2[0], q2[1], q2[2], q2[3]);
            shp3[wid] = make_float4(q3[0], q3[1], q3[2], q3[3]);
        }

        // ---- producers signal; warp0 reduces + publishes coefficients ----
        if (wid != 0) {
            BAR_ARRIVE(1);                // 480 arrivals
            BAR_SYNC(2);                  // wait for coefficients
        } else {
            BAR_SYNC(1);                  // +32 -> 512: all partials visible
            const float4 z = make_float4(0.f, 0.f, 0.f, 0.f);
            float4 v1 = (lane < NWARP) ? shp1[lane] : z;
            float4 v2 = (lane < NWARP) ? shp2[lane] : z;
            float4 v3 = (lane < NWARP) ? shp3[lane] : z;
            #pragma unroll
            for (int off = 8; off > 0; off >>= 1) {
                v1.x += __shfl_xor_sync(0xFFFFFFFFu, v1.x, off);
                v1.y += __shfl_xor_sync(0xFFFFFFFFu, v1.y, off);
                v1.z += __shfl_xor_sync(0xFFFFFFFFu, v1.z, off);
                v1.w += __shfl_xor_sync(0xFFFFFFFFu, v1.w, off);
                v2.x += __shfl_xor_sync(0xFFFFFFFFu, v2.x, off);
                v2.y += __shfl_xor_sync(0xFFFFFFFFu, v2.y, off);
                v2.z += __shfl_xor_sync(0xFFFFFFFFu, v2.z, off);
                v2.w += __shfl_xor_sync(0xFFFFFFFFu, v2.w, off);
                v3.x += __shfl_xor_sync(0xFFFFFFFFu, v3.x, off);
                v3.y += __shfl_xor_sync(0xFFFFFFFFu, v3.y, off);
                v3.z += __shfl_xor_sync(0xFFFFFFFFu, v3.z, off);
                v3.w += __shfl_xor_sync(0xFFFFFFFFu, v3.w, off);
            }
            if (lane == 0) {
                const float c12 = sh_k[0], c13 = sh_k[1], c23 = sh_k[2];
                const float d1[R] = {v1.x, v1.y, v1.z, v1.w};
                const float d2[R] = {v2.x, v2.y, v2.z, v2.w};
                const float d3[R] = {v3.x, v3.y, v3.z, v3.w};
                #pragma unroll
                for (int r = 0; r < R; ++r) {
                    const float a1 = d1[r] + 1.0f;
                    const float a2 = fmaf(a1, d2[r], c12) + 1.0f;
                    const float a3 = fmaf(a2, fmaf(a1, d3[r], c13), c23) + 1.0f;
                    const float k1 = a2 * a3;
                    const float m  = a1 * k1;
                    sh_c[r] = make_float4(m, k1, a3, 0.0f);
                }
            }
            __syncwarp();
            BAR_ARRIVE(2);                // 32 arrivals: publish coefficients
        }

        // ---- epilogue: out = m*x + k1*b1 + k2*b2 + b3 (x re-read via LDS) ----
        const float4 bv1 = sb1[t];
        const float4 bv2 = sb2[t];
        const int base = tile * TILE_F4 + t;
        #pragma unroll
        for (int r = 0; r < R; ++r) {
            const float4 c  = sh_c[r];
            const float4 xv = cb[r * VEC + t];
            float4 o;
            o.x = fmaf(xv.x, c.x, fmaf(bv1.x, c.y, fmaf(bv2.x, c.z, bv3.x)));
            o.y = fmaf(xv.y, c.x, fmaf(bv1.y, c.y, fmaf(bv2.y, c.z, bv3.y)));
            o.z = fmaf(xv.z, c.x, fmaf(bv1.z, c.y, fmaf(bv2.z, c.z, bv3.z)));
            o.w = fmaf(xv.w, c.x, fmaf(bv1.w, c.y, fmaf(bv2.w, c.z, bv3.w)));
            __stcs(&out[base + r * VEC], o);
        }

        ++stage; if (stage >= NSTAGE) stage = 0;
    }
}

extern "C" void kernel_launch(void* const* d_in, const int* in_sizes, int n_in,
                              void* d_out, int out_size)
{
    const float4* x  = (const float4*)d_in[0];
    const float4* w1 = (const float4*)d_in[1];
    const float4* b1 = (const float4*)d_in[2];
    const float4* w2 = (const float4*)d_in[3];
    const float4* b2 = (const float4*)d_in[4];
    const float4* w3 = (const float4*)d_in[5];
    const float4* b3 = (const float4*)d_in[6];
    float4* out = (float4*)d_out;

    cudaFuncSetAttribute(crossnet_kernel,
                         cudaFuncAttributeMaxDynamicSharedMemorySize, DYN_BYTES);

    const int B = in_sizes[0] / D;    // 16384
    const int ntiles = B / R;         // 4096
    const int grid = (ntiles < NCTA) ? ntiles : NCTA;
    crossnet_kernel<<<grid, THREADS, DYN_BYTES>>>(x, w1, b1, w2, b2, w3, b3, out, ntiles);
}

// round 17
// speedup vs baseline: 1.5526x; 1.1024x over previous
#include <cuda_runtime.h>

// CrossNet closed form, persistent SMALL CTAs (256 thr, 4/SM) + register
// double-buffer pipeline + split named barriers. 4 independent barrier
// domains per SM keep DRAM request flow continuous through reduce windows.
//   d_k = x . w_k ; c12=b1.w2, c13=b1.w3, c23=b2.w3 (prologue, per CTA)
//   a1 = d1+1; a2 = a1*d2+c12+1; a3 = a2*(a1*d3+c13)+c23+1
//   out = (a1*a2*a3)*x + (a2*a3)*b1 + a3*b2 + b3
// B=16384, D=2048 fp32. R=2 rows/tile, thread owns cols t and t+256.
// Barrier protocol (256 total arrivals each):
//   bar1: warps 1..7 arrive (224) + warp0 sync (32)
//   bar2: warp0 arrive (32) + warps 1..7 sync (224)

#define D 2048
#define VEC (D / 4)            // 512 float4 per row
#define THREADS 256
#define NWARP (THREADS / 32)   // 8
#define R 2
#define C 2                    // float4 chunks per thread per row
#define NCTA 592               // 4 per SM * 148 SMs
#define DYN_BYTES (6 * VEC * 16)   // w1,w2,w3,b1,b2,b3 = 48 KB

#define BAR_ARRIVE(id) asm volatile("bar.arrive %0, %1;" :: "r"(id), "r"(THREADS) : "memory")
#define BAR_SYNC(id)   asm volatile("bar.sync %0, %1;"   :: "r"(id), "r"(THREADS) : "memory")

__device__ __forceinline__ float dot4(float4 a, float4 b) {
    return a.x*b.x + a.y*b.y + a.z*b.z + a.w*b.w;
}

__global__ __launch_bounds__(THREADS, 4)
void crossnet_kernel(const float4* __restrict__ x,
                     const float4* __restrict__ w1, const float4* __restrict__ b1,
                     const float4* __restrict__ w2, const float4* __restrict__ b2,
                     const float4* __restrict__ w3, const float4* __restrict__ b3,
                     float4* __restrict__ out, int ntiles)
{
    extern __shared__ float4 dyn[];
    float4* sw1 = dyn;             // [VEC]
    float4* sw2 = sw1 + VEC;
    float4* sw3 = sw2 + VEC;
    float4* sb1 = sw3 + VEC;
    float4* sb2 = sb1 + VEC;
    float4* sb3 = sb2 + VEC;

    __shared__ float2 shp1[NWARP], shp2[NWARP], shp3[NWARP]; // per-warp partials (2 rows)
    __shared__ float4 sh_c[R];                               // per-row (m, k1, k2, _)
    __shared__ float  sh_k[3];                               // c12, c13, c23

    const int t    = threadIdx.x;
    const int lane = t & 31;
    const int wid  = t >> 5;

    // ---- prologue: stage w/b in smem + cross constants ----
    {
        float q12 = 0.f, q13 = 0.f, q23 = 0.f;
        #pragma unroll
        for (int c = 0; c < C; ++c) {
            const int i = t + c * THREADS;
            const float4 wq1 = __ldg(&w1[i]);
            const float4 wq2 = __ldg(&w2[i]);
            const float4 wq3 = __ldg(&w3[i]);
            const float4 bq1 = __ldg(&b1[i]);
            const float4 bq2 = __ldg(&b2[i]);
            const float4 bq3 = __ldg(&b3[i]);
            sw1[i] = wq1; sw2[i] = wq2; sw3[i] = wq3;
            sb1[i] = bq1; sb2[i] = bq2; sb3[i] = bq3;
            q12 += dot4(bq1, wq2);
            q13 += dot4(bq1, wq3);
            q23 += dot4(bq2, wq3);
        }
        #pragma unroll
        for (int off = 16; off > 0; off >>= 1) {
            q12 += __shfl_xor_sync(0xFFFFFFFFu, q12, off);
            q13 += __shfl_xor_sync(0xFFFFFFFFu, q13, off);
            q23 += __shfl_xor_sync(0xFFFFFFFFu, q23, off);
        }
        if (lane == 0) { shp1[wid] = make_float2(q12, q13); shp2[wid] = make_float2(q23, 0.f); }
    }
    __syncthreads();
    if (wid == 0) {
        float a = (lane < NWARP) ? shp1[lane].x : 0.f;
        float b = (lane < NWARP) ? shp1[lane].y : 0.f;
        float c = (lane < NWARP) ? shp2[lane].x : 0.f;
        #pragma unroll
        for (int off = 4; off > 0; off >>= 1) {
            a += __shfl_xor_sync(0xFFFFFFFFu, a, off);
            b += __shfl_xor_sync(0xFFFFFFFFu, b, off);
            c += __shfl_xor_sync(0xFFFFFFFFu, c, off);
        }
        if (lane == 0) { sh_k[0] = a; sh_k[1] = b; sh_k[2] = c; }
    }

    // ---- pipeline prologue: load first tile ----
    int tile = blockIdx.x;
    float4 yc[R][C];
    if (tile < ntiles) {
        #pragma unroll
        for (int r = 0; r < R; ++r)
            #pragma unroll
            for (int c = 0; c < C; ++c)
                yc[r][c] = __ldcs(&x[(tile * R + r) * VEC + t + c * THREADS]);
    }
    __syncthreads();

    for (; tile < ntiles; tile += gridDim.x) {
        // ---- issue NEXT tile's loads at loop TOP (hidden under dots+reduce) ----
        const int nxt = tile + gridDim.x;
        float4 yn[R][C];
        if (nxt < ntiles) {
            #pragma unroll
            for (int r = 0; r < R; ++r)
                #pragma unroll
                for (int c = 0; c < C; ++c)
                    yn[r][c] = __ldcs(&x[(nxt * R + r) * VEC + t + c * THREADS]);
        }

        // ---- three dots per row (weights via LDS; 2 chunks per thread) ----
        float p1[R], p2[R], p3[R];
        #pragma unroll
        for (int r = 0; r < R; ++r) { p1[r] = 0.f; p2[r] = 0.f; p3[r] = 0.f; }
        #pragma unroll
        for (int c = 0; c < C; ++c) {
            const int i = t + c * THREADS;
            const float4 wq1 = sw1[i];
            const float4 wq2 = sw2[i];
            const float4 wq3 = sw3[i];
            #pragma unroll
            for (int r = 0; r < R; ++r) {
                p1[r] += dot4(yc[r][c], wq1);
                p2[r] += dot4(yc[r][c], wq2);
                p3[r] += dot4(yc[r][c], wq3);
            }
        }
        #pragma unroll
        for (int off = 16; off > 0; off >>= 1) {
            #pragma unroll
            for (int r = 0; r < R; ++r) {
                p1[r] += __shfl_xor_sync(0xFFFFFFFFu, p1[r], off);
                p2[r] += __shfl_xor_sync(0xFFFFFFFFu, p2[r], off);
                p3[r] += __shfl_xor_sync(0xFFFFFFFFu, p3[r], off);
            }
        }
        if (lane == 0) {
            shp1[wid] = make_float2(p1[0], p1[1]);
            shp2[wid] = make_float2(p2[0], p2[1]);
            shp3[wid] = make_float2(p3[0], p3[1]);
        }

        // ---- producers signal; warp0 reduces + publishes coefficients ----
        if (wid != 0) {
            BAR_ARRIVE(1);                // 224 arrivals
            BAR_SYNC(2);                  // wait for coefficients (yn in flight)
        } else {
            BAR_SYNC(1);                  // +32 -> 256: all partials visible
            const float2 z = make_float2(0.f, 0.f);
            float2 v1 = (lane < NWARP) ? shp1[lane] : z;
            float2 v2 = (lane < NWARP) ? shp2[lane] : z;
            float2 v3 = (lane < NWARP) ? shp3[lane] : z;
            #pragma unroll
            for (int off = 4; off > 0; off >>= 1) {
                v1.x += __shfl_xor_sync(0xFFFFFFFFu, v1.x, off);
                v1.y += __shfl_xor_sync(0xFFFFFFFFu, v1.y, off);
                v2.x += __shfl_xor_sync(0xFFFFFFFFu, v2.x, off);
                v2.y += __shfl_xor_sync(0xFFFFFFFFu, v2.y, off);
                v3.x += __shfl_xor_sync(0xFFFFFFFFu, v3.x, off);
                v3.y += __shfl_xor_sync(0xFFFFFFFFu, v3.y, off);
            }
            if (lane == 0) {
                const float c12 = sh_k[0], c13 = sh_k[1], c23 = sh_k[2];
                const float d1[R] = {v1.x, v1.y};
                const float d2[R] = {v2.x, v2.y};
                const float d3[R] = {v3.x, v3.y};
                #pragma unroll
                for (int r = 0; r < R; ++r) {
                    const float a1 = d1[r] + 1.0f;
                    const float a2 = fmaf(a1, d2[r], c12) + 1.0f;
                    const float a3 = fmaf(a2, fmaf(a1, d3[r], c13), c23) + 1.0f;
                    const float k1 = a2 * a3;
                    const float m  = a1 * k1;
                    sh_c[r] = make_float4(m, k1, a3, 0.0f);
                }
            }
            __syncwarp();
            BAR_ARRIVE(2);                // 32 arrivals: publish coefficients
        }

        // ---- epilogue: out = m*x + k1*b1 + k2*b2 + b3 ----
        #pragma unroll
        for (int c = 0; c < C; ++c) {
            const int i = t + c * THREADS;
            const float4 bv1 = sb1[i];
            const float4 bv2 = sb2[i];
            const float4 bv3 = sb3[i];
            #pragma unroll
            for (int r = 0; r < R; ++r) {
                const float4 cf = sh_c[r];
                const float4 xv = yc[r][c];
                float4 o;
                o.x = fmaf(xv.x, cf.x, fmaf(bv1.x, cf.y, fmaf(bv2.x, cf.z, bv3.x)));
                o.y = fmaf(xv.y, cf.x, fmaf(bv1.y, cf.y, fmaf(bv2.y, cf.z, bv3.y)));
                o.z = fmaf(xv.z, cf.x, fmaf(bv1.z, cf.y, fmaf(bv2.z, cf.z, bv3.z)));
                o.w = fmaf(xv.w, cf.x, fmaf(bv1.w, cf.y, fmaf(bv2.w, cf.z, bv3.w)));
                __stcs(&out[(tile * R + r) * VEC + i], o);
            }
        }

        // ---- rotate pipeline ----
        #pragma unroll
        for (int r = 0; r < R; ++r)
            #pragma unroll
            for (int c = 0; c < C; ++c)
                yc[r][c] = yn[r][c];
    }
}

extern "C" void kernel_launch(void* const* d_in, const int* in_sizes, int n_in,
                              void* d_out, int out_size)
{
    const float4* x  = (const float4*)d_in[0];
    const float4* w1 = (const float4*)d_in[1];
    const float4* b1 = (const float4*)d_in[2];
    const float4* w2 = (const float4*)d_in[3];
    const float4* b2 = (const float4*)d_in[4];
    const float4* w3 = (const float4*)d_in[5];
    const float4* b3 = (const float4*)d_in[6];
    float4* out = (float4*)d_out;

    cudaFuncSetAttribute(crossnet_kernel,
                         cudaFuncAttributeMaxDynamicSharedMemorySize, DYN_BYTES);

    const int B = in_sizes[0] / D;    // 16384
    const int ntiles = B / R;         // 8192
    const int grid = (ntiles < NCTA) ? ntiles : NCTA;
    crossnet_kernel<<<grid, THREADS, DYN_BYTES>>>(x, w1, b1, w2, b2, w3, b3, out, ntiles);
}